// round 1
// baseline (speedup 1.0000x reference)
#include <cuda_runtime.h>
#include <math.h>

#define B_   256
#define N_   300
#define T_   64
#define FIN  3
#define U_   256
#define G_   1024            // 4*U_
#define K0   900             // N_*FIN
#define M_   16384           // B_*T_
#define FOUT 2
#define ND   600             // N_*FOUT

// ---------------- scratch (static device globals; no allocation) ----------------
__device__ float    g_xr[(size_t)M_ * K0];   // transposed input  (B*T, 900)   ~59MB
__device__ float    g_zx[(size_t)M_ * G_];   // gate pre-acts     (B*T, 1024)  ~67MB
__device__ float    g_h0[(size_t)M_ * U_];   // layer-0 h sequence             ~17MB
__device__ float    g_h1[(size_t)M_ * U_];   // layer-1 h sequence             ~17MB
__device__ unsigned g_bar[2];                // grid-barrier counters

// ---------------- barrier reset ----------------
__global__ void reset_bar_kernel() {
    g_bar[0] = 0u;
    g_bar[1] = 0u;
}

// ---------------- input transpose: x (B,N,T,F) -> xr (B*T, N*F) ----------------
__global__ void transpose_x_kernel(const float* __restrict__ x) {
    long i = (long)blockIdx.x * blockDim.x + threadIdx.x;
    if (i >= (long)M_ * K0) return;
    int  col = (int)(i % K0);       // n*FIN + f
    long row = i / K0;              // b*T + t
    int f = col % FIN;
    int n = col / FIN;
    int t = (int)(row & (T_ - 1));
    int b = (int)(row >> 6);        // T_ = 64
    g_xr[i] = x[(((long)b * N_ + n) * T_ + t) * FIN + f];
}

// ---------------- tiled fp32 GEMM: C(MxN) = A(MxK) @ Bm(KxN) + bias ----------------
// BM=BN=64, BK=16, 256 threads, 4x4 microtile.
// SCATTER=true: epilogue writes the final output with the (B,T,N*2)->(B,N,T,2) permute.
template <bool SCATTER>
__global__ void gemm_kernel(const float* __restrict__ A, const float* __restrict__ Bm,
                            const float* __restrict__ bias, float* __restrict__ C,
                            int M, int N, int K) {
    __shared__ float As[16][68];
    __shared__ float Bs[16][68];

    const int m0 = blockIdx.y * 64;
    const int n0 = blockIdx.x * 64;
    const int tid = threadIdx.x;
    const int tn = tid & 15;   // 0..15
    const int tm = tid >> 4;   // 0..15

    float acc[4][4];
#pragma unroll
    for (int i = 0; i < 4; i++)
#pragma unroll
        for (int j = 0; j < 4; j++) acc[i][j] = 0.f;

    for (int k0 = 0; k0 < K; k0 += 16) {
        // load A tile 64x16 (store k-major)
#pragma unroll
        for (int p = 0; p < 4; p++) {
            int idx = tid + p * 256;
            int k = idx & 15, m = idx >> 4;
            As[k][m] = (k0 + k < K) ? A[(long)(m0 + m) * K + (k0 + k)] : 0.f;
        }
        // load B tile 16x64
#pragma unroll
        for (int p = 0; p < 4; p++) {
            int idx = tid + p * 256;
            int n = idx & 63, k = idx >> 6;
            Bs[k][n] = (k0 + k < K && n0 + n < N) ? Bm[(long)(k0 + k) * N + (n0 + n)] : 0.f;
        }
        __syncthreads();
#pragma unroll
        for (int kk = 0; kk < 16; kk++) {
            float4 a = *(const float4*)&As[kk][tm * 4];
            float4 b = *(const float4*)&Bs[kk][tn * 4];
            acc[0][0] += a.x * b.x; acc[0][1] += a.x * b.y; acc[0][2] += a.x * b.z; acc[0][3] += a.x * b.w;
            acc[1][0] += a.y * b.x; acc[1][1] += a.y * b.y; acc[1][2] += a.y * b.z; acc[1][3] += a.y * b.w;
            acc[2][0] += a.z * b.x; acc[2][1] += a.z * b.y; acc[2][2] += a.z * b.z; acc[2][3] += a.z * b.w;
            acc[3][0] += a.w * b.x; acc[3][1] += a.w * b.y; acc[3][2] += a.w * b.z; acc[3][3] += a.w * b.w;
        }
        __syncthreads();
    }

#pragma unroll
    for (int i = 0; i < 4; i++) {
        int m = m0 + tm * 4 + i;
#pragma unroll
        for (int j = 0; j < 4; j++) {
            int n = n0 + tn * 4 + j;
            if (n < N) {
                float v = acc[i][j] + bias[n];
                if (SCATTER) {
                    // m = b*T + t ; n = nn*2 + fo ; out[b][nn][t][fo]
                    int b = m >> 6, t = m & 63;
                    int nn = n >> 1, fo = n & 1;
                    C[(((long)b * N_ + nn) * T_ + t) * FOUT + fo] = v;
                } else {
                    C[(long)m * N + n] = v;
                }
            }
        }
    }
}

// ---------------- persistent LSTM layer kernel ----------------
// grid = 128 blocks (16 batch-tiles of 16 x 8 unit-tiles of 32), 128 threads/block.
// Each block: keeps its 128 U columns in smem (128KB, loaded once), cell state in regs,
// exchanges h through global hseq with a software grid barrier each step.
__global__ void lstm_kernel(const float* __restrict__ zx,   // (M_,1024) rows b*T+t, bias included
                            const float* __restrict__ Uw,   // (256,1024)
                            float* __restrict__ hseq,       // (M_,256)  rows b*T+t
                            int bar_idx) {
    extern __shared__ float smem[];
    float* Us = smem;                 // [k][u*4+g]  256*128 floats
    float* Hs = smem + 256 * 128;     // [k][b] pitch 20 -> 256*20 floats

    const int tid  = threadIdx.x;     // 0..127
    const int ublk = blockIdx.x & 7;
    const int bblk = blockIdx.x >> 3;
    const int u0 = ublk * 32;
    const int b0 = bblk * 16;
    const int cg = tid & 31;          // unit within tile
    const int bg = tid >> 5;          // batch group (0..3): batches bg*4..bg*4+3

    // Load U slice once: Us[k][u*4+g] = U[k][g*256 + u0 + u]
    for (int idx = tid; idx < 256 * 128; idx += 128) {
        int u = idx & 31;
        int g = (idx >> 5) & 3;
        int k = idx >> 7;
        Us[k * 128 + u * 4 + g] = Uw[(long)k * G_ + g * U_ + u0 + u];
    }
    __syncthreads();

    float cst[4] = {0.f, 0.f, 0.f, 0.f};
    unsigned* bar = &g_bar[bar_idx];
    const unsigned nb = gridDim.x;

    for (int t = 0; t < T_; t++) {
        // init gates from precomputed zx (issued early to overlap with Hs staging)
        float z[4][4];
#pragma unroll
        for (int i = 0; i < 4; i++) {
            long row = (long)(b0 + bg * 4 + i) * T_ + t;
            const float* zp = zx + row * G_ + (u0 + cg);
#pragma unroll
            for (int g = 0; g < 4; g++) z[i][g] = __ldg(&zp[g * U_]);
        }

        if (t > 0) {
            // stage h_{t-1} tile: Hs[k][b], pitch 20
            for (int idx = tid; idx < 16 * 256; idx += 128) {
                int b = idx >> 8;
                int k = idx & 255;
                Hs[k * 20 + b] = __ldcg(&hseq[((long)(b0 + b) * T_ + (t - 1)) * U_ + k]);
            }
            __syncthreads();
#pragma unroll 4
            for (int k = 0; k < 256; k++) {
                float4 a = *(const float4*)&Hs[k * 20 + bg * 4];
                float4 b = *(const float4*)&Us[k * 128 + cg * 4];
                z[0][0] += a.x * b.x; z[0][1] += a.x * b.y; z[0][2] += a.x * b.z; z[0][3] += a.x * b.w;
                z[1][0] += a.y * b.x; z[1][1] += a.y * b.y; z[1][2] += a.y * b.z; z[1][3] += a.y * b.w;
                z[2][0] += a.z * b.x; z[2][1] += a.z * b.y; z[2][2] += a.z * b.z; z[2][3] += a.z * b.w;
                z[3][0] += a.w * b.x; z[3][1] += a.w * b.y; z[3][2] += a.w * b.z; z[3][3] += a.w * b.w;
            }
        }

        // gate nonlinearities + state update (gate order: i, f, g, o)
#pragma unroll
        for (int i = 0; i < 4; i++) {
            float ig = 1.f / (1.f + expf(-z[i][0]));
            float fg = 1.f / (1.f + expf(-z[i][1]));
            float gg = fmaxf(z[i][2], 0.f);
            float og = 1.f / (1.f + expf(-z[i][3]));
            float c  = fg * cst[i] + ig * gg;
            cst[i] = c;
            float h = og * fmaxf(c, 0.f);
            hseq[((long)(b0 + bg * 4 + i) * T_ + t) * U_ + (u0 + cg)] = h;
        }

        // grid barrier (monotonic counter) before any block reads h_t
        if (t < T_ - 1) {
            __threadfence();
            __syncthreads();
            if (tid == 0) {
                atomicAdd(bar, 1u);
                unsigned target = nb * (unsigned)(t + 1);
                volatile unsigned* vb = bar;
                while (*vb < target) { __nanosleep(64); }
            }
            __syncthreads();
        }
    }
}

// ---------------- host launcher ----------------
extern "C" void kernel_launch(void* const* d_in, const int* in_sizes, int n_in,
                              void* d_out, int out_size) {
    const float* x  = (const float*)d_in[0];
    const float* W0 = (const float*)d_in[1];
    const float* U0 = (const float*)d_in[2];
    const float* b0 = (const float*)d_in[3];
    const float* W1 = (const float*)d_in[4];
    const float* U1 = (const float*)d_in[5];
    const float* b1 = (const float*)d_in[6];
    const float* Wd = (const float*)d_in[7];
    const float* bd = (const float*)d_in[8];
    float* out = (float*)d_out;

    float *xr_p, *zx_p, *h0_p, *h1_p;
    cudaGetSymbolAddress((void**)&xr_p, g_xr);
    cudaGetSymbolAddress((void**)&zx_p, g_zx);
    cudaGetSymbolAddress((void**)&h0_p, g_h0);
    cudaGetSymbolAddress((void**)&h1_p, g_h1);

    const int LSTM_SMEM = (256 * 128 + 256 * 20) * (int)sizeof(float); // 148KB
    cudaFuncSetAttribute(lstm_kernel, cudaFuncAttributeMaxDynamicSharedMemorySize, LSTM_SMEM);

    // 0) reset grid-barrier counters
    reset_bar_kernel<<<1, 1>>>();

    // 1) transpose x -> xr (B*T, 900)
    {
        long total = (long)M_ * K0;
        int blocks = (int)((total + 255) / 256);
        transpose_x_kernel<<<blocks, 256>>>(x);
    }

    // 2) zx = xr @ W0 + b0   (16384 x 1024, K=900)
    gemm_kernel<false><<<dim3(G_ / 64, M_ / 64), 256>>>(xr_p, W0, b0, zx_p, M_, G_, K0);

    // 3) LSTM layer 0 -> g_h0
    lstm_kernel<<<128, 128, LSTM_SMEM>>>(zx_p, U0, h0_p, 0);

    // 4) zx = h0 @ W1 + b1   (16384 x 1024, K=256)
    gemm_kernel<false><<<dim3(G_ / 64, M_ / 64), 256>>>(h0_p, W1, b1, zx_p, M_, G_, U_);

    // 5) LSTM layer 1 -> g_h1
    lstm_kernel<<<128, 128, LSTM_SMEM>>>(zx_p, U1, h1_p, 1);

    // 6) out = h1 @ Wd + bd, scattered to (B, N, T, 2)
    gemm_kernel<true><<<dim3((ND + 63) / 64, M_ / 64), 256>>>(h1_p, Wd, bd, out, M_, ND, U_);
}

// round 2
// speedup vs baseline: 1.3558x; 1.3558x over previous
#include <cuda_runtime.h>
#include <math.h>

#define B_   256
#define N_   300
#define T_   64
#define FIN  3
#define U_   256
#define G_   1024            // 4*U_
#define K0   900             // N_*FIN
#define M_   16384           // B_*T_
#define FOUT 2
#define ND   600             // N_*FOUT

// ---------------- scratch (static device globals; no allocation) ----------------
__device__ float    g_xr[(size_t)M_ * K0];   // transposed input  (B*T, 900)
__device__ float    g_zx[(size_t)M_ * G_];   // gate pre-acts     (B*T, 1024)
__device__ float    g_h0[(size_t)M_ * U_];   // layer-0 h sequence
__device__ float    g_h1[(size_t)M_ * U_];   // layer-1 h sequence
__device__ unsigned g_bar[2];                // grid-barrier counters

__global__ void reset_bar_kernel() {
    g_bar[0] = 0u;
    g_bar[1] = 0u;
}

// ---------------- input transpose: x (B,N,T,F) -> xr (B*T, N*F) ----------------
__global__ void transpose_x_kernel(const float* __restrict__ x) {
    long i = (long)blockIdx.x * blockDim.x + threadIdx.x;
    if (i >= (long)M_ * K0) return;
    int  col = (int)(i % K0);       // n*FIN + f
    long row = i / K0;              // b*T + t
    int f = col % FIN;
    int n = col / FIN;
    int t = (int)(row & (T_ - 1));
    int b = (int)(row >> 6);        // T_ = 64
    g_xr[i] = x[(((long)b * N_ + n) * T_ + t) * FIN + f];
}

// ---------------- tiled fp32 GEMM: C(MxN) = A(MxK) @ Bm(KxN) + bias ----------------
// BM=128, BN=64, BK=16, 256 threads, 8x4 microtile (FMA-bound: 32 FMA / 3 LDS.128).
// SCATTER=true: epilogue writes final output with (B,T,N*2)->(B,N,T,2) permute.
template <bool SCATTER>
__global__ void gemm_kernel(const float* __restrict__ A, const float* __restrict__ Bm,
                            const float* __restrict__ bias, float* __restrict__ C,
                            int M, int N, int K) {
    __shared__ float As[16][132];   // [k][m], pitch 132 (16B-aligned rows)
    __shared__ float Bs[16][68];    // [k][n]

    const int m0 = blockIdx.y * 128;
    const int n0 = blockIdx.x * 64;
    const int tid = threadIdx.x;
    const int tn = tid & 15;   // 0..15 -> 4 n each
    const int tm = tid >> 4;   // 0..15 -> 8 m each

    float acc[8][4];
#pragma unroll
    for (int i = 0; i < 8; i++)
#pragma unroll
        for (int j = 0; j < 4; j++) acc[i][j] = 0.f;

    for (int k0 = 0; k0 < K; k0 += 16) {
        // A tile 128x16: 512 float4, 2 per thread (K%4==0 so float4 all-or-nothing)
#pragma unroll
        for (int u = 0; u < 2; u++) {
            int fidx = tid + u * 256;
            int m = fidx >> 2;
            int k = (fidx & 3) * 4;
            float4 v = make_float4(0.f, 0.f, 0.f, 0.f);
            if (k0 + k < K) v = *(const float4*)&A[(long)(m0 + m) * K + k0 + k];
            As[k][m] = v.x; As[k + 1][m] = v.y; As[k + 2][m] = v.z; As[k + 3][m] = v.w;
        }
        // B tile 16x64: 256 float4, 1 per thread
        {
            int n = (tid & 15) * 4;
            int k = tid >> 4;
            float4 v = make_float4(0.f, 0.f, 0.f, 0.f);
            if (k0 + k < K && n0 + n < N) v = *(const float4*)&Bm[(long)(k0 + k) * N + n0 + n];
            *(float4*)&Bs[k][n] = v;
        }
        __syncthreads();
#pragma unroll
        for (int kk = 0; kk < 16; kk++) {
            float4 a0 = *(const float4*)&As[kk][tm * 8];
            float4 a1 = *(const float4*)&As[kk][tm * 8 + 4];
            float4 b  = *(const float4*)&Bs[kk][tn * 4];
            float am[8] = {a0.x, a0.y, a0.z, a0.w, a1.x, a1.y, a1.z, a1.w};
            float bn[4] = {b.x, b.y, b.z, b.w};
#pragma unroll
            for (int i = 0; i < 8; i++)
#pragma unroll
                for (int j = 0; j < 4; j++) acc[i][j] += am[i] * bn[j];
        }
        __syncthreads();
    }

#pragma unroll
    for (int i = 0; i < 8; i++) {
        int m = m0 + tm * 8 + i;
#pragma unroll
        for (int j = 0; j < 4; j++) {
            int n = n0 + tn * 4 + j;
            if (n < N) {
                float v = acc[i][j] + bias[n];
                if (SCATTER) {
                    int b = m >> 6, t = m & 63;
                    int nn = n >> 1, fo = n & 1;
                    C[(((long)b * N_ + nn) * T_ + t) * FOUT + fo] = v;
                } else {
                    C[(long)m * N + n] = v;
                }
            }
        }
    }
}

// ---------------- persistent LSTM layer kernel ----------------
// 128 blocks (16 batch-tiles x 8 unit-tiles) x 256 threads.
// Thread: 2 batches x 1 unit x 4 gates. Us slice (128KB) in smem, cell state in regs,
// h exchanged via global hseq + software grid barrier per step.
#define HS_PITCH 18
__global__ void __launch_bounds__(256, 1)
lstm_kernel(const float* __restrict__ zx,   // (M_,1024) rows b*T+t (bias folded)
            const float* __restrict__ Uw,   // (256,1024)
            float* __restrict__ hseq,       // (M_,256)  rows b*T+t
            int bar_idx) {
    extern __shared__ float smem[];
    float* Us = smem;                       // [k][u*4+g]  256*128 floats
    float* Hs = smem + 256 * 128;           // [k][b] pitch HS_PITCH

    const int tid  = threadIdx.x;           // 0..255
    const int ublk = blockIdx.x & 7;
    const int bblk = blockIdx.x >> 3;
    const int u0 = ublk * 32;
    const int b0 = bblk * 16;
    const int cg = tid & 31;                // unit within tile
    const int bg = tid >> 5;                // 0..7: batches bg*2, bg*2+1

    // Load U slice once: Us[k][u*4+g] = U[k][g*256 + u0 + u]
    for (int idx = tid; idx < 256 * 128; idx += 256) {
        int u = idx & 31;
        int g = (idx >> 5) & 3;
        int k = idx >> 7;
        Us[k * 128 + u * 4 + g] = Uw[(long)k * G_ + g * U_ + u0 + u];
    }
    __syncthreads();

    float cst[2] = {0.f, 0.f};
    unsigned* bar = &g_bar[bar_idx];
    const unsigned nb = gridDim.x;

    // prefetch z for t=0
    float z[2][4];
#pragma unroll
    for (int i = 0; i < 2; i++) {
        const float* zp = zx + ((long)(b0 + bg * 2 + i) * T_ + 0) * G_ + (u0 + cg);
#pragma unroll
        for (int g = 0; g < 4; g++) z[i][g] = __ldg(&zp[g * U_]);
    }

    for (int t = 0; t < T_; t++) {
        if (t > 0) {
            // stage h_{t-1}: Hs[k][b]. b-fastest mapping: coalesced 32B/row LDG,
            // ~2-way STS conflicts.
#pragma unroll
            for (int g4 = 0; g4 < 4; g4++) {
                int idx = tid + g4 * 256;          // 0..1023
                int b  = idx & 15;
                int kq = idx >> 4;                 // 0..63
                int k  = kq * 4;
                float4 v = *(const float4*)__builtin_assume_aligned(
                    (const void*)&hseq[((long)(b0 + b) * T_ + (t - 1)) * U_ + k], 16);
                Hs[(k + 0) * HS_PITCH + b] = v.x;
                Hs[(k + 1) * HS_PITCH + b] = v.y;
                Hs[(k + 2) * HS_PITCH + b] = v.z;
                Hs[(k + 3) * HS_PITCH + b] = v.w;
            }
            __syncthreads();
#pragma unroll 8
            for (int k = 0; k < 256; k++) {
                float2 a = *(const float2*)&Hs[k * HS_PITCH + bg * 2];
                float4 b = *(const float4*)&Us[k * 128 + cg * 4];
                z[0][0] += a.x * b.x; z[0][1] += a.x * b.y; z[0][2] += a.x * b.z; z[0][3] += a.x * b.w;
                z[1][0] += a.y * b.x; z[1][1] += a.y * b.y; z[1][2] += a.y * b.z; z[1][3] += a.y * b.w;
            }
        }

        // gates (i, f, g, o) + state update + h store
#pragma unroll
        for (int i = 0; i < 2; i++) {
            float ig = 1.f / (1.f + expf(-z[i][0]));
            float fg = 1.f / (1.f + expf(-z[i][1]));
            float gg = fmaxf(z[i][2], 0.f);
            float og = 1.f / (1.f + expf(-z[i][3]));
            float c  = fg * cst[i] + ig * gg;
            cst[i] = c;
            float h = og * fmaxf(c, 0.f);
            hseq[((long)(b0 + bg * 2 + i) * T_ + t) * U_ + (u0 + cg)] = h;
        }

        if (t < T_ - 1) {
            // prefetch z for t+1 (overlaps DRAM latency with the barrier wait)
#pragma unroll
            for (int i = 0; i < 2; i++) {
                const float* zp = zx + ((long)(b0 + bg * 2 + i) * T_ + (t + 1)) * G_ + (u0 + cg);
#pragma unroll
                for (int g = 0; g < 4; g++) z[i][g] = __ldg(&zp[g * U_]);
            }
            // grid barrier (monotonic counter)
            __threadfence();
            __syncthreads();
            if (tid == 0) {
                atomicAdd(bar, 1u);
                unsigned target = nb * (unsigned)(t + 1);
                volatile unsigned* vb = bar;
                while (*vb < target) { __nanosleep(64); }
            }
            __syncthreads();
        }
    }
}

// ---------------- host launcher ----------------
extern "C" void kernel_launch(void* const* d_in, const int* in_sizes, int n_in,
                              void* d_out, int out_size) {
    const float* x  = (const float*)d_in[0];
    const float* W0 = (const float*)d_in[1];
    const float* U0 = (const float*)d_in[2];
    const float* b0 = (const float*)d_in[3];
    const float* W1 = (const float*)d_in[4];
    const float* U1 = (const float*)d_in[5];
    const float* b1 = (const float*)d_in[6];
    const float* Wd = (const float*)d_in[7];
    const float* bd = (const float*)d_in[8];
    float* out = (float*)d_out;

    float *xr_p, *zx_p, *h0_p, *h1_p;
    cudaGetSymbolAddress((void**)&xr_p, g_xr);
    cudaGetSymbolAddress((void**)&zx_p, g_zx);
    cudaGetSymbolAddress((void**)&h0_p, g_h0);
    cudaGetSymbolAddress((void**)&h1_p, g_h1);

    const int LSTM_SMEM = (256 * 128 + 256 * HS_PITCH) * (int)sizeof(float); // ~149KB
    cudaFuncSetAttribute(lstm_kernel, cudaFuncAttributeMaxDynamicSharedMemorySize, LSTM_SMEM);

    reset_bar_kernel<<<1, 1>>>();

    {
        long total = (long)M_ * K0;
        int blocks = (int)((total + 255) / 256);
        transpose_x_kernel<<<blocks, 256>>>(x);
    }

    // zx = xr @ W0 + b0   (16384 x 1024, K=900)
    gemm_kernel<false><<<dim3(G_ / 64, M_ / 128), 256>>>(xr_p, W0, b0, zx_p, M_, G_, K0);

    // LSTM layer 0 -> g_h0
    lstm_kernel<<<128, 256, LSTM_SMEM>>>(zx_p, U0, h0_p, 0);

    // zx = h0 @ W1 + b1   (16384 x 1024, K=256)
    gemm_kernel<false><<<dim3(G_ / 64, M_ / 128), 256>>>(h0_p, W1, b1, zx_p, M_, G_, U_);

    // LSTM layer 1 -> g_h1
    lstm_kernel<<<128, 256, LSTM_SMEM>>>(zx_p, U1, h1_p, 1);

    // out = h1 @ Wd + bd, scattered to (B, N, T, 2)
    gemm_kernel<true><<<dim3((ND + 63) / 64, M_ / 128), 256>>>(h1_p, Wd, bd, out, M_, ND, U_);
}

// round 5
// speedup vs baseline: 1.8991x; 1.4007x over previous
#include <cuda_runtime.h>
#include <cuda_bf16.h>
#include <math.h>
#include <stdint.h>

#define B_   256
#define N_   300
#define T_   64
#define FIN  3
#define U_   256
#define G_   1024            // 4*U_
#define K0   900             // N_*FIN
#define K0P  960             // padded to multiple of 64
#define M_   16384           // B_*T_
#define FOUT 2
#define ND   600             // N_*FOUT

// ---------------- scratch (static device globals; no allocation) ----------------
__device__ __nv_bfloat16 g_ahi[(size_t)M_ * K0P];   // x transposed, bf16-hi
__device__ __nv_bfloat16 g_alo[(size_t)M_ * K0P];   // x transposed, bf16-lo
__device__ __nv_bfloat16 g_bhi[(size_t)G_ * K0P];   // weight K-major, bf16-hi (max size)
__device__ __nv_bfloat16 g_blo[(size_t)G_ * K0P];
__device__ __nv_bfloat16 g_hhi[(size_t)M_ * U_];    // h bf16-hi (next GEMM's A operand)
__device__ __nv_bfloat16 g_hlo[(size_t)M_ * U_];
__device__ float    g_zx[(size_t)M_ * G_];          // gate pre-acts
__device__ float    g_h0[(size_t)M_ * U_];          // layer-0 h sequence (fp32 recurrence)
__device__ float    g_h1[(size_t)M_ * U_];
__device__ unsigned g_bar[2];

__global__ void reset_bar_kernel() { g_bar[0] = 0u; g_bar[1] = 0u; }

// single dynamic-smem symbol for all kernels
extern __shared__ char dynsmem[];

// ---------------- bf16 2-term split ----------------
__device__ __forceinline__ void bf16split(float v, __nv_bfloat16& hi, __nv_bfloat16& lo) {
    hi = __float2bfloat16(v);
    lo = __float2bfloat16(v - __bfloat162float(hi));
}

// ---------------- input transpose + split: x (B,N,T,F) -> (B*T, 960) bf16 hi/lo ----------------
__global__ void transpose_x_kernel(const float* __restrict__ x) {
    long i = (long)blockIdx.x * blockDim.x + threadIdx.x;
    if (i >= (long)M_ * K0P) return;
    int  col = (int)(i % K0P);
    long row = i / K0P;
    float v = 0.f;
    if (col < K0) {
        int f = col % FIN;
        int n = col / FIN;
        int t = (int)(row & (T_ - 1));
        int b = (int)(row >> 6);
        v = x[(((long)b * N_ + n) * T_ + t) * FIN + f];
    }
    __nv_bfloat16 hi, lo;
    bf16split(v, hi, lo);
    g_ahi[i] = hi;
    g_alo[i] = lo;
}

// ---------------- weight transpose + split: W (K,N) -> (N, Ks) K-major bf16 hi/lo ----------------
__global__ void wtrans_kernel(const float* __restrict__ W, int K, int N, int Ks) {
    long i = (long)blockIdx.x * blockDim.x + threadIdx.x;
    if (i >= (long)N * Ks) return;
    int k = (int)(i % Ks);
    int n = (int)(i / Ks);
    float v = (k < K) ? W[(long)k * N + n] : 0.f;
    __nv_bfloat16 hi, lo;
    bf16split(v, hi, lo);
    g_bhi[i] = hi;
    g_blo[i] = lo;
}

// ================= mma.sync helpers =================
__device__ __forceinline__ uint32_t smem_u32(const void* p) {
    uint32_t a;
    asm("{ .reg .u64 t; cvta.to.shared.u64 t, %1; cvt.u32.u64 %0, t; }" : "=r"(a) : "l"(p));
    return a;
}
__device__ __forceinline__ uint32_t sw128(uint32_t o) { return o ^ ((o >> 3) & 0x70); }

__device__ __forceinline__ void ldsm_x4(uint32_t addr, uint32_t& r0, uint32_t& r1,
                                        uint32_t& r2, uint32_t& r3) {
    asm volatile("ldmatrix.sync.aligned.m8n8.x4.shared.b16 {%0,%1,%2,%3}, [%4];"
                 : "=r"(r0), "=r"(r1), "=r"(r2), "=r"(r3) : "r"(addr));
}

__device__ __forceinline__ void mma_bf16(float* d, const uint32_t* a, uint32_t b0, uint32_t b1) {
    asm volatile(
        "mma.sync.aligned.m16n8k16.row.col.f32.bf16.bf16.f32 "
        "{%0,%1,%2,%3}, {%4,%5,%6,%7}, {%8,%9}, {%0,%1,%2,%3};"
        : "+f"(d[0]), "+f"(d[1]), "+f"(d[2]), "+f"(d[3])
        : "r"(a[0]), "r"(a[1]), "r"(a[2]), "r"(a[3]), "r"(b0), "r"(b1));
}

// ---------------- tensor-core GEMM: C(M x N) = A @ B^T + bias ----------------
// A: (M, Ks) bf16 hi/lo row-major.  B: (N rows, Ks) bf16 hi/lo K-major.
// Tile 128x128, BK=64 halves (128B rows, SW128), 256 threads = 8 warps (2m x 4n),
// warp does 64x32 via 4x4 m16n8k16 fragments; 3 split-term MMAs each.
#define SM_A_HI 0
#define SM_A_LO 16384
#define SM_B_HI 32768
#define SM_B_LO 49152
#define MM_SMEM 65536

template <bool SCATTER>
__global__ void __launch_bounds__(256, 2)
mma_gemm_kernel(const __nv_bfloat16* __restrict__ Ahi, const __nv_bfloat16* __restrict__ Alo,
                const __nv_bfloat16* __restrict__ Bhi, const __nv_bfloat16* __restrict__ Blo,
                const float* __restrict__ bias, float* __restrict__ C,
                int Ks, int N) {
    char* smem = dynsmem;
    const int tid  = threadIdx.x;
    const int lane = tid & 31;
    const int wid  = tid >> 5;
    const int warp_m = wid >> 2;       // 0..1 -> 64 rows
    const int warp_n = wid & 3;        // 0..3 -> 32 cols
    const int m0 = blockIdx.y * 128;
    const int n0 = blockIdx.x * 128;
    const uint32_t sbase = smem_u32(smem);

    float acc[4][4][4];                // [mf][nf][quad]
#pragma unroll
    for (int i = 0; i < 4; i++)
#pragma unroll
        for (int j = 0; j < 4; j++)
#pragma unroll
            for (int q = 0; q < 4; q++) acc[i][j][q] = 0.f;

    for (int kt = 0; kt < Ks; kt += 64) {
        // ---- stage 128x64 tiles of A(hi,lo) and B(hi,lo), SW128-swizzled ----
#pragma unroll
        for (int i = 0; i < 4; i++) {
            int idx = tid + i * 256;            // 0..1023
            int r = idx >> 3, kq = idx & 7;     // row, 16B chunk
            uint32_t so = sw128((uint32_t)(r * 128 + kq * 16));
            const uint4 va_h = *(const uint4*)(Ahi + (size_t)(m0 + r) * Ks + kt + kq * 8);
            const uint4 va_l = *(const uint4*)(Alo + (size_t)(m0 + r) * Ks + kt + kq * 8);
            *(uint4*)(smem + SM_A_HI + so) = va_h;
            *(uint4*)(smem + SM_A_LO + so) = va_l;
            uint4 vb_h = make_uint4(0u, 0u, 0u, 0u), vb_l = make_uint4(0u, 0u, 0u, 0u);
            if (n0 + r < N) {
                vb_h = *(const uint4*)(Bhi + (size_t)(n0 + r) * Ks + kt + kq * 8);
                vb_l = *(const uint4*)(Blo + (size_t)(n0 + r) * Ks + kt + kq * 8);
            }
            *(uint4*)(smem + SM_B_HI + so) = vb_h;
            *(uint4*)(smem + SM_B_LO + so) = vb_l;
        }
        __syncthreads();

#pragma unroll
        for (int ks = 0; ks < 4; ks++) {
            const int kb = ks * 16;             // halves offset within the 64-wide row

            // ---- B fragments: 2 n16-groups x (hi,lo), ldmatrix.x4 each ----
            // lane mapping: matrices (n0..7,kb),(n0..7,kb+8),(n8..15,kb),(n8..15,kb+8)
            uint32_t bh[2][4], bl[2][4];
#pragma unroll
            for (int ng = 0; ng < 2; ng++) {
                int nrow = warp_n * 32 + ng * 16 + (lane & 7) + (lane >> 4) * 8;
                int koff = kb + ((lane >> 3) & 1) * 8;
                uint32_t so = sw128((uint32_t)(nrow * 128 + koff * 2));
                ldsm_x4(sbase + SM_B_HI + so, bh[ng][0], bh[ng][1], bh[ng][2], bh[ng][3]);
                ldsm_x4(sbase + SM_B_LO + so, bl[ng][0], bl[ng][1], bl[ng][2], bl[ng][3]);
            }

            // ---- per m-fragment: load A hi/lo, 12 MMAs ----
#pragma unroll
            for (int mf = 0; mf < 4; mf++) {
                int mrow = warp_m * 64 + mf * 16 + (lane & 7) + ((lane >> 3) & 1) * 8;
                int koff = kb + (lane >> 4) * 8;
                uint32_t so = sw128((uint32_t)(mrow * 128 + koff * 2));
                uint32_t ah[4], al[4];
                ldsm_x4(sbase + SM_A_HI + so, ah[0], ah[1], ah[2], ah[3]);
                ldsm_x4(sbase + SM_A_LO + so, al[0], al[1], al[2], al[3]);
#pragma unroll
                for (int ng = 0; ng < 2; ng++) {
#pragma unroll
                    for (int h = 0; h < 2; h++) {
                        int nf = ng * 2 + h;
                        mma_bf16(acc[mf][nf], ah, bh[ng][h * 2], bh[ng][h * 2 + 1]);
                        mma_bf16(acc[mf][nf], ah, bl[ng][h * 2], bl[ng][h * 2 + 1]);
                        mma_bf16(acc[mf][nf], al, bh[ng][h * 2], bh[ng][h * 2 + 1]);
                    }
                }
            }
        }
        __syncthreads();
    }

    // ---- epilogue: direct float2 stores from fragments ----
    const int g   = lane >> 2;
    const int tq  = lane & 3;
#pragma unroll
    for (int mf = 0; mf < 4; mf++) {
#pragma unroll
        for (int nf = 0; nf < 4; nf++) {
            int c = n0 + warp_n * 32 + nf * 8 + tq * 2;
            if (c >= N) continue;
            float bx = bias[c], by = bias[c + 1];
#pragma unroll
            for (int half = 0; half < 2; half++) {
                int m = m0 + warp_m * 64 + mf * 16 + g + half * 8;
                float vx = acc[mf][nf][half * 2 + 0] + bx;
                float vy = acc[mf][nf][half * 2 + 1] + by;
                if (SCATTER) {
                    int b = m >> 6, t = m & 63;
                    int nn = c >> 1;
                    float2* p = (float2*)&C[(((long)b * N_ + nn) * T_ + t) * FOUT];
                    *p = make_float2(vx, vy);
                } else {
                    *(float2*)&C[(size_t)m * N + c] = make_float2(vx, vy);
                }
            }
        }
    }
}

// ---------------- persistent LSTM layer kernel -------------
#define HS_PITCH 18
__global__ void __launch_bounds__(256, 1)
lstm_kernel(const float* __restrict__ zx,   // (M_,1024) rows b*T+t (bias folded)
            const float* __restrict__ Uw,   // (256,1024)
            float* __restrict__ hseq,       // (M_,256)  rows b*T+t
            int bar_idx) {
    float* smem = (float*)dynsmem;
    float* Us = smem;                       // [k][u*4+g]  256*128 floats
    float* Hs = smem + 256 * 128;           // [k][b] pitch HS_PITCH

    const int tid  = threadIdx.x;           // 0..255
    const int ublk = blockIdx.x & 7;
    const int bblk = blockIdx.x >> 3;
    const int u0 = ublk * 32;
    const int b0 = bblk * 16;
    const int cg = tid & 31;
    const int bg = tid >> 5;

    for (int idx = tid; idx < 256 * 128; idx += 256) {
        int u = idx & 31;
        int g = (idx >> 5) & 3;
        int k = idx >> 7;
        Us[k * 128 + u * 4 + g] = Uw[(long)k * G_ + g * U_ + u0 + u];
    }
    __syncthreads();

    float cst[2] = {0.f, 0.f};
    unsigned* bar = &g_bar[bar_idx];
    const unsigned nb = gridDim.x;

    float z[2][4];
#pragma unroll
    for (int i = 0; i < 2; i++) {
        const float* zp = zx + ((long)(b0 + bg * 2 + i) * T_ + 0) * G_ + (u0 + cg);
#pragma unroll
        for (int g = 0; g < 4; g++) z[i][g] = __ldg(&zp[g * U_]);
    }

    for (int t = 0; t < T_; t++) {
        if (t > 0) {
#pragma unroll
            for (int g4 = 0; g4 < 4; g4++) {
                int idx = tid + g4 * 256;
                int b  = idx & 15;
                int kq = idx >> 4;
                int k  = kq * 4;
                float4 v = *(const float4*)&hseq[((long)(b0 + b) * T_ + (t - 1)) * U_ + k];
                Hs[(k + 0) * HS_PITCH + b] = v.x;
                Hs[(k + 1) * HS_PITCH + b] = v.y;
                Hs[(k + 2) * HS_PITCH + b] = v.z;
                Hs[(k + 3) * HS_PITCH + b] = v.w;
            }
            __syncthreads();
#pragma unroll 8
            for (int k = 0; k < 256; k++) {
                float2 a = *(const float2*)&Hs[k * HS_PITCH + bg * 2];
                float4 b = *(const float4*)&Us[k * 128 + cg * 4];
                z[0][0] += a.x * b.x; z[0][1] += a.x * b.y; z[0][2] += a.x * b.z; z[0][3] += a.x * b.w;
                z[1][0] += a.y * b.x; z[1][1] += a.y * b.y; z[1][2] += a.y * b.z; z[1][3] += a.y * b.w;
            }
        }

#pragma unroll
        for (int i = 0; i < 2; i++) {
            float ig = 1.f / (1.f + expf(-z[i][0]));
            float fg = 1.f / (1.f + expf(-z[i][1]));
            float gg = fmaxf(z[i][2], 0.f);
            float og = 1.f / (1.f + expf(-z[i][3]));
            float c  = fg * cst[i] + ig * gg;
            cst[i] = c;
            float h = og * fmaxf(c, 0.f);
            long m = (long)(b0 + bg * 2 + i) * T_ + t;
            hseq[m * U_ + (u0 + cg)] = h;
            __nv_bfloat16 hi, lo;
            bf16split(h, hi, lo);
            g_hhi[m * U_ + (u0 + cg)] = hi;
            g_hlo[m * U_ + (u0 + cg)] = lo;
        }

        if (t < T_ - 1) {
#pragma unroll
            for (int i = 0; i < 2; i++) {
                const float* zp = zx + ((long)(b0 + bg * 2 + i) * T_ + (t + 1)) * G_ + (u0 + cg);
#pragma unroll
                for (int g = 0; g < 4; g++) z[i][g] = __ldg(&zp[g * U_]);
            }
            __threadfence();
            __syncthreads();
            if (tid == 0) {
                atomicAdd(bar, 1u);
                unsigned target = nb * (unsigned)(t + 1);
                volatile unsigned* vb = bar;
                while (*vb < target) { __nanosleep(64); }
            }
            __syncthreads();
        }
    }
}

// ---------------- host launcher ----------------
extern "C" void kernel_launch(void* const* d_in, const int* in_sizes, int n_in,
                              void* d_out, int out_size) {
    const float* x  = (const float*)d_in[0];
    const float* W0 = (const float*)d_in[1];
    const float* U0 = (const float*)d_in[2];
    const float* b0 = (const float*)d_in[3];
    const float* W1 = (const float*)d_in[4];
    const float* U1 = (const float*)d_in[5];
    const float* b1 = (const float*)d_in[6];
    const float* Wd = (const float*)d_in[7];
    const float* bd = (const float*)d_in[8];
    float* out = (float*)d_out;

    __nv_bfloat16 *ahi, *alo, *bhi, *blo, *hhi, *hlo;
    float *zx_p, *h0_p, *h1_p;
    cudaGetSymbolAddress((void**)&ahi, g_ahi);
    cudaGetSymbolAddress((void**)&alo, g_alo);
    cudaGetSymbolAddress((void**)&bhi, g_bhi);
    cudaGetSymbolAddress((void**)&blo, g_blo);
    cudaGetSymbolAddress((void**)&hhi, g_hhi);
    cudaGetSymbolAddress((void**)&hlo, g_hlo);
    cudaGetSymbolAddress((void**)&zx_p, g_zx);
    cudaGetSymbolAddress((void**)&h0_p, g_h0);
    cudaGetSymbolAddress((void**)&h1_p, g_h1);

    const int LSTM_SMEM = (256 * 128 + 256 * HS_PITCH) * (int)sizeof(float);
    cudaFuncSetAttribute(lstm_kernel, cudaFuncAttributeMaxDynamicSharedMemorySize, LSTM_SMEM);
    cudaFuncSetAttribute(mma_gemm_kernel<false>, cudaFuncAttributeMaxDynamicSharedMemorySize, MM_SMEM);
    cudaFuncSetAttribute(mma_gemm_kernel<true>,  cudaFuncAttributeMaxDynamicSharedMemorySize, MM_SMEM);

    reset_bar_kernel<<<1, 1>>>();

    // x -> (B*T, 960) bf16 hi/lo
    {
        long total = (long)M_ * K0P;
        transpose_x_kernel<<<(int)((total + 255) / 256), 256>>>(x);
    }
    // W0 -> (1024, 960) K-major hi/lo
    {
        long total = (long)G_ * K0P;
        wtrans_kernel<<<(int)((total + 255) / 256), 256>>>(W0, K0, G_, K0P);
    }
    // zx = x @ W0 + b0
    mma_gemm_kernel<false><<<dim3(G_ / 128, M_ / 128), 256, MM_SMEM>>>(
        ahi, alo, bhi, blo, b0, zx_p, K0P, G_);

    // LSTM layer 0 -> g_h0 (+ g_hhi/g_hlo)
    lstm_kernel<<<128, 256, LSTM_SMEM>>>(zx_p, U0, h0_p, 0);

    // W1 -> (1024, 256) K-major hi/lo
    {
        long total = (long)G_ * U_;
        wtrans_kernel<<<(int)((total + 255) / 256), 256>>>(W1, U_, G_, U_);
    }
    // zx = h0 @ W1 + b1
    mma_gemm_kernel<false><<<dim3(G_ / 128, M_ / 128), 256, MM_SMEM>>>(
        hhi, hlo, bhi, blo, b1, zx_p, U_, G_);

    // LSTM layer 1 -> g_h1 (+ g_hhi/g_hlo overwritten with h1)
    lstm_kernel<<<128, 256, LSTM_SMEM>>>(zx_p, U1, h1_p, 1);

    // Wd -> (600, 256) K-major hi/lo
    {
        long total = (long)ND * U_;
        wtrans_kernel<<<(int)((total + 255) / 256), 256>>>(Wd, U_, ND, U_);
    }
    // out = h1 @ Wd + bd, scattered to (B, N, T, 2)
    mma_gemm_kernel<true><<<dim3((ND + 127) / 128, M_ / 128), 256, MM_SMEM>>>(
        hhi, hlo, bhi, blo, bd, out, U_, ND);
}

// round 6
// speedup vs baseline: 2.9506x; 1.5537x over previous
#include <cuda_runtime.h>
#include <cuda_bf16.h>
#include <math.h>
#include <stdint.h>

#define B_   256
#define N_   300
#define T_   64
#define FIN  3
#define U_   256
#define G_   1024            // 4*U_
#define K0   900             // N_*FIN
#define K0P  960             // padded to multiple of 64
#define M_   16384           // B_*T_
#define FOUT 2
#define ND   600             // N_*FOUT

// ---------------- scratch (static device globals; no allocation) ----------------
__device__ __nv_bfloat16 g_ahi[(size_t)M_ * K0P];   // x transposed, bf16-hi
__device__ __nv_bfloat16 g_alo[(size_t)M_ * K0P];   // x transposed, bf16-lo
__device__ __nv_bfloat16 g_bhi[(size_t)G_ * K0P];   // weight K-major, bf16-hi (max size)
__device__ __nv_bfloat16 g_blo[(size_t)G_ * K0P];
__device__ __nv_bfloat16 g_uhi[(size_t)G_ * U_];    // recurrent U, permuted K-major, hi
__device__ __nv_bfloat16 g_ulo[(size_t)G_ * U_];
__device__ __nv_bfloat16 g_hhi[(size_t)M_ * U_];    // h sequence bf16-hi
__device__ __nv_bfloat16 g_hlo[(size_t)M_ * U_];    // h sequence bf16-lo
__device__ float    g_zx[(size_t)M_ * G_];          // gate pre-acts
__device__ unsigned g_bar[2];

__global__ void reset_bar_kernel() { g_bar[0] = 0u; g_bar[1] = 0u; }

// single dynamic-smem symbol for all kernels
extern __shared__ char dynsmem[];

// ---------------- bf16 2-term split ----------------
__device__ __forceinline__ void bf16split(float v, __nv_bfloat16& hi, __nv_bfloat16& lo) {
    hi = __float2bfloat16(v);
    lo = __float2bfloat16(v - __bfloat162float(hi));
}

// ---------------- input transpose + split ----------------
__global__ void transpose_x_kernel(const float* __restrict__ x) {
    long i = (long)blockIdx.x * blockDim.x + threadIdx.x;
    if (i >= (long)M_ * K0P) return;
    int  col = (int)(i % K0P);
    long row = i / K0P;
    float v = 0.f;
    if (col < K0) {
        int f = col % FIN;
        int n = col / FIN;
        int t = (int)(row & (T_ - 1));
        int b = (int)(row >> 6);
        v = x[(((long)b * N_ + n) * T_ + t) * FIN + f];
    }
    __nv_bfloat16 hi, lo;
    bf16split(v, hi, lo);
    g_ahi[i] = hi;
    g_alo[i] = lo;
}

// ---------------- weight transpose + split: W (K,N) -> (N, Ks) K-major hi/lo ----------------
__global__ void wtrans_kernel(const float* __restrict__ W, int K, int N, int Ks) {
    long i = (long)blockIdx.x * blockDim.x + threadIdx.x;
    if (i >= (long)N * Ks) return;
    int k = (int)(i % Ks);
    int n = (int)(i / Ks);
    float v = (k < K) ? W[(long)k * N + n] : 0.f;
    __nv_bfloat16 hi, lo;
    bf16split(v, hi, lo);
    g_bhi[i] = hi;
    g_blo[i] = lo;
}

// ---------------- recurrent-U permute + split: U (256,1024) -> (1024 perm, 256) K-major ----
// col_perm -> (gate, unit): ublk=cp>>7, local=cp&127, warp_n=local>>5, rem=local&31,
// gate=rem>>3, ul=rem&7, unit=ublk*32+warp_n*8+ul, orig col = gate*256+unit.
__global__ void utrans_kernel(const float* __restrict__ U) {
    long i = (long)blockIdx.x * blockDim.x + threadIdx.x;
    if (i >= (long)G_ * U_) return;
    int k  = (int)(i & 255);
    int cp = (int)(i >> 8);
    int ublk = cp >> 7;
    int local = cp & 127;
    int warp_n = local >> 5;
    int rem = local & 31;
    int gate = rem >> 3;
    int ul = rem & 7;
    int unit = ublk * 32 + warp_n * 8 + ul;
    float v = U[(long)k * G_ + gate * U_ + unit];
    __nv_bfloat16 hi, lo;
    bf16split(v, hi, lo);
    g_uhi[i] = hi;
    g_ulo[i] = lo;
}

// ================= mma.sync helpers =================
__device__ __forceinline__ uint32_t smem_u32(const void* p) {
    uint32_t a;
    asm("{ .reg .u64 t; cvta.to.shared.u64 t, %1; cvt.u32.u64 %0, t; }" : "=r"(a) : "l"(p));
    return a;
}
__device__ __forceinline__ uint32_t sw128(uint32_t o) { return o ^ ((o >> 3) & 0x70); }

__device__ __forceinline__ void ldsm_x4(uint32_t addr, uint32_t& r0, uint32_t& r1,
                                        uint32_t& r2, uint32_t& r3) {
    asm volatile("ldmatrix.sync.aligned.m8n8.x4.shared.b16 {%0,%1,%2,%3}, [%4];"
                 : "=r"(r0), "=r"(r1), "=r"(r2), "=r"(r3) : "r"(addr));
}

__device__ __forceinline__ void mma_bf16(float* d, const uint32_t* a, uint32_t b0, uint32_t b1) {
    asm volatile(
        "mma.sync.aligned.m16n8k16.row.col.f32.bf16.bf16.f32 "
        "{%0,%1,%2,%3}, {%4,%5,%6,%7}, {%8,%9}, {%0,%1,%2,%3};"
        : "+f"(d[0]), "+f"(d[1]), "+f"(d[2]), "+f"(d[3])
        : "r"(a[0]), "r"(a[1]), "r"(a[2]), "r"(a[3]), "r"(b0), "r"(b1));
}

// ---------------- tensor-core GEMM (feed-forward): C = A @ B^T + bias ----------------
#define SM_A_HI 0
#define SM_A_LO 16384
#define SM_B_HI 32768
#define SM_B_LO 49152
#define MM_SMEM 65536

template <bool SCATTER>
__global__ void __launch_bounds__(256, 2)
mma_gemm_kernel(const __nv_bfloat16* __restrict__ Ahi, const __nv_bfloat16* __restrict__ Alo,
                const __nv_bfloat16* __restrict__ Bhi, const __nv_bfloat16* __restrict__ Blo,
                const float* __restrict__ bias, float* __restrict__ C,
                int Ks, int N) {
    char* smem = dynsmem;
    const int tid  = threadIdx.x;
    const int lane = tid & 31;
    const int wid  = tid >> 5;
    const int warp_m = wid >> 2;       // 0..1 -> 64 rows
    const int warp_n = wid & 3;        // 0..3 -> 32 cols
    const int m0 = blockIdx.y * 128;
    const int n0 = blockIdx.x * 128;
    const uint32_t sbase = smem_u32(smem);

    float acc[4][4][4];
#pragma unroll
    for (int i = 0; i < 4; i++)
#pragma unroll
        for (int j = 0; j < 4; j++)
#pragma unroll
            for (int q = 0; q < 4; q++) acc[i][j][q] = 0.f;

    for (int kt = 0; kt < Ks; kt += 64) {
#pragma unroll
        for (int i = 0; i < 4; i++) {
            int idx = tid + i * 256;
            int r = idx >> 3, kq = idx & 7;
            uint32_t so = sw128((uint32_t)(r * 128 + kq * 16));
            const uint4 va_h = *(const uint4*)(Ahi + (size_t)(m0 + r) * Ks + kt + kq * 8);
            const uint4 va_l = *(const uint4*)(Alo + (size_t)(m0 + r) * Ks + kt + kq * 8);
            *(uint4*)(smem + SM_A_HI + so) = va_h;
            *(uint4*)(smem + SM_A_LO + so) = va_l;
            uint4 vb_h = make_uint4(0u, 0u, 0u, 0u), vb_l = make_uint4(0u, 0u, 0u, 0u);
            if (n0 + r < N) {
                vb_h = *(const uint4*)(Bhi + (size_t)(n0 + r) * Ks + kt + kq * 8);
                vb_l = *(const uint4*)(Blo + (size_t)(n0 + r) * Ks + kt + kq * 8);
            }
            *(uint4*)(smem + SM_B_HI + so) = vb_h;
            *(uint4*)(smem + SM_B_LO + so) = vb_l;
        }
        __syncthreads();

#pragma unroll
        for (int ks = 0; ks < 4; ks++) {
            const int kb = ks * 16;
            uint32_t bh[2][4], bl[2][4];
#pragma unroll
            for (int ng = 0; ng < 2; ng++) {
                int nrow = warp_n * 32 + ng * 16 + (lane & 7) + (lane >> 4) * 8;
                int koff = kb + ((lane >> 3) & 1) * 8;
                uint32_t so = sw128((uint32_t)(nrow * 128 + koff * 2));
                ldsm_x4(sbase + SM_B_HI + so, bh[ng][0], bh[ng][1], bh[ng][2], bh[ng][3]);
                ldsm_x4(sbase + SM_B_LO + so, bl[ng][0], bl[ng][1], bl[ng][2], bl[ng][3]);
            }
#pragma unroll
            for (int mf = 0; mf < 4; mf++) {
                int mrow = warp_m * 64 + mf * 16 + (lane & 7) + ((lane >> 3) & 1) * 8;
                int koff = kb + (lane >> 4) * 8;
                uint32_t so = sw128((uint32_t)(mrow * 128 + koff * 2));
                uint32_t ah[4], al[4];
                ldsm_x4(sbase + SM_A_HI + so, ah[0], ah[1], ah[2], ah[3]);
                ldsm_x4(sbase + SM_A_LO + so, al[0], al[1], al[2], al[3]);
#pragma unroll
                for (int ng = 0; ng < 2; ng++) {
#pragma unroll
                    for (int h = 0; h < 2; h++) {
                        int nf = ng * 2 + h;
                        mma_bf16(acc[mf][nf], ah, bh[ng][h * 2], bh[ng][h * 2 + 1]);
                        mma_bf16(acc[mf][nf], ah, bl[ng][h * 2], bl[ng][h * 2 + 1]);
                        mma_bf16(acc[mf][nf], al, bh[ng][h * 2], bh[ng][h * 2 + 1]);
                    }
                }
            }
        }
        __syncthreads();
    }

    const int g  = lane >> 2;
    const int tq = lane & 3;
#pragma unroll
    for (int mf = 0; mf < 4; mf++) {
#pragma unroll
        for (int nf = 0; nf < 4; nf++) {
            int c = n0 + warp_n * 32 + nf * 8 + tq * 2;
            if (c >= N) continue;
            float bx = bias[c], by = bias[c + 1];
#pragma unroll
            for (int half = 0; half < 2; half++) {
                int m = m0 + warp_m * 64 + mf * 16 + g + half * 8;
                float vx = acc[mf][nf][half * 2 + 0] + bx;
                float vy = acc[mf][nf][half * 2 + 1] + by;
                if (SCATTER) {
                    int b = m >> 6, t = m & 63;
                    int nn = c >> 1;
                    float2* p = (float2*)&C[(((long)b * N_ + nn) * T_ + t) * FOUT];
                    *p = make_float2(vx, vy);
                } else {
                    *(float2*)&C[(size_t)m * N + c] = make_float2(vx, vy);
                }
            }
        }
    }
}

// ---------------- tensor-core persistent LSTM layer kernel ----------------
// 128 blocks = 16 batch-tiles (M=16) x 8 unit-tiles (128 permuted gate-cols).
// 128 threads (4 warps, each 32 permuted cols = 8 units x 4 gates).
// U slice in smem (SW128 panels), per step: stage h tile, 16 k-chunks x 12 HMMA,
// thread-local gates (permutation puts all 4 gates of a unit in one thread),
// h written as packed bf16 hi/lo (doubles as next GEMM's A operand).
#define SM_U_HI  0                    // 4 panels x 16KB
#define SM_U_LO  65536
#define SM_H_HI  131072               // 4 panels x 2KB
#define SM_H_LO  139264
#define LSTM_SMEM 147456

__global__ void __launch_bounds__(128, 1)
lstm_kernel(const float* __restrict__ zx,   // (M_,1024) rows b*T+t, cols gate*256+unit
            const __nv_bfloat16* __restrict__ Uphi,  // permuted (1024,256) K-major
            const __nv_bfloat16* __restrict__ Uplo,
            __nv_bfloat16* __restrict__ hhi,         // (M_,256) rows b*T+t
            __nv_bfloat16* __restrict__ hlo,
            int bar_idx) {
    char* smem = dynsmem;
    const uint32_t sbase = smem_u32(smem);
    const int tid  = threadIdx.x;
    const int lane = tid & 31;
    const int warp_n = tid >> 5;            // 0..3
    const int ublk = blockIdx.x & 7;
    const int bblk = blockIdx.x >> 3;
    const int b0 = bblk * 16;
    const int cbase = ublk * 128;           // permuted col base

    // ---- load U slice into smem panels (once) ----
    for (int idx = tid; idx < 4096; idx += 128) {
        int n = idx >> 5, kq = idx & 31;
        int k = kq * 8;
        int p = k >> 6, ko = k & 63;
        uint32_t dst = (uint32_t)(p * 16384) + sw128((uint32_t)(n * 128 + ko * 2));
        *(uint4*)(smem + SM_U_HI + dst) = *(const uint4*)(Uphi + (size_t)(cbase + n) * U_ + k);
        *(uint4*)(smem + SM_U_LO + dst) = *(const uint4*)(Uplo + (size_t)(cbase + n) * U_ + k);
    }
    __syncthreads();

    const int g  = lane >> 2;               // row group 0..7
    const int tq = lane & 3;
    const int ubase = ublk * 32 + warp_n * 8 + tq * 2;   // global unit for e=0

    unsigned* bar = &g_bar[bar_idx];
    const unsigned nb = gridDim.x;

    float cst[4] = {0.f, 0.f, 0.f, 0.f};    // c for q = half*2+e
    float zq[4][4];                          // zx prefetch [gate nf][q]

    // prefetch zx for t=0
#pragma unroll
    for (int half = 0; half < 2; half++) {
        long row = (long)(b0 + half * 8 + g) * T_ + 0;
#pragma unroll
        for (int nf = 0; nf < 4; nf++) {
            float2 v = *(const float2*)&zx[row * G_ + nf * U_ + ubase];
            zq[nf][half * 2 + 0] = v.x;
            zq[nf][half * 2 + 1] = v.y;
        }
    }

    for (int t = 0; t < T_; t++) {
        float acc[4][4];
#pragma unroll
        for (int nf = 0; nf < 4; nf++)
#pragma unroll
            for (int q = 0; q < 4; q++) acc[nf][q] = 0.f;

        if (t > 0) {
            // ---- stage h_{t-1} tile: 16 rows x 256 k, hi+lo, into panels ----
#pragma unroll
            for (int j = 0; j < 4; j++) {
                int idx = tid + j * 128;         // 0..511
                int r = idx >> 5, kq = idx & 31;
                int k = kq * 8;
                int p = k >> 6, ko = k & 63;
                long src = ((long)(b0 + r) * T_ + (t - 1)) * U_ + k;
                uint32_t dst = (uint32_t)(p * 2048) + sw128((uint32_t)(r * 128 + ko * 2));
                *(uint4*)(smem + SM_H_HI + dst) = *(const uint4*)(hhi + src);
                *(uint4*)(smem + SM_H_LO + dst) = *(const uint4*)(hlo + src);
            }
            __syncthreads();

            // ---- 16 k-chunks x (1 A-frag pair + 2 B-frag pairs + 12 HMMA) ----
#pragma unroll
            for (int kc = 0; kc < 16; kc++) {
                const int p = kc >> 2;
                const int kb = (kc & 3) * 16;
                // A (h tile)
                int mrow = (lane & 7) + ((lane >> 3) & 1) * 8;
                int koffA = kb + (lane >> 4) * 8;
                uint32_t soA = (uint32_t)(p * 2048) + sw128((uint32_t)(mrow * 128 + koffA * 2));
                uint32_t ah[4], al[4];
                ldsm_x4(sbase + SM_H_HI + soA, ah[0], ah[1], ah[2], ah[3]);
                ldsm_x4(sbase + SM_H_LO + soA, al[0], al[1], al[2], al[3]);
                // B (U slice)
                uint32_t bh[2][4], bl[2][4];
#pragma unroll
                for (int ng = 0; ng < 2; ng++) {
                    int nrow = warp_n * 32 + ng * 16 + (lane & 7) + (lane >> 4) * 8;
                    int koffB = kb + ((lane >> 3) & 1) * 8;
                    uint32_t soB = (uint32_t)(p * 16384) + sw128((uint32_t)(nrow * 128 + koffB * 2));
                    ldsm_x4(sbase + SM_U_HI + soB, bh[ng][0], bh[ng][1], bh[ng][2], bh[ng][3]);
                    ldsm_x4(sbase + SM_U_LO + soB, bl[ng][0], bl[ng][1], bl[ng][2], bl[ng][3]);
                }
#pragma unroll
                for (int ng = 0; ng < 2; ng++) {
#pragma unroll
                    for (int h = 0; h < 2; h++) {
                        int nf = ng * 2 + h;
                        mma_bf16(acc[nf], ah, bh[ng][h * 2], bh[ng][h * 2 + 1]);
                        mma_bf16(acc[nf], ah, bl[ng][h * 2], bl[ng][h * 2 + 1]);
                        mma_bf16(acc[nf], al, bh[ng][h * 2], bh[ng][h * 2 + 1]);
                    }
                }
            }
        }

        // ---- gates (i,f,g,o) + state update + packed bf16 h store ----
#pragma unroll
        for (int half = 0; half < 2; half++) {
            long row = (long)(b0 + half * 8 + g) * T_ + t;
            __nv_bfloat16 phi[2], plo[2];
#pragma unroll
            for (int e = 0; e < 2; e++) {
                int q = half * 2 + e;
                float ig = 1.f / (1.f + expf(-(zq[0][q] + acc[0][q])));
                float fg = 1.f / (1.f + expf(-(zq[1][q] + acc[1][q])));
                float gg = fmaxf(zq[2][q] + acc[2][q], 0.f);
                float og = 1.f / (1.f + expf(-(zq[3][q] + acc[3][q])));
                float c  = fg * cst[q] + ig * gg;
                cst[q] = c;
                float h = og * fmaxf(c, 0.f);
                bf16split(h, phi[e], plo[e]);
            }
            *(uint32_t*)&hhi[row * U_ + ubase] = ((uint32_t)*(uint16_t*)&phi[1] << 16) |
                                                 (uint32_t)*(uint16_t*)&phi[0];
            *(uint32_t*)&hlo[row * U_ + ubase] = ((uint32_t)*(uint16_t*)&plo[1] << 16) |
                                                 (uint32_t)*(uint16_t*)&plo[0];
        }

        if (t < T_ - 1) {
            // prefetch zx for t+1 (overlaps with barrier wait)
#pragma unroll
            for (int half = 0; half < 2; half++) {
                long row = (long)(b0 + half * 8 + g) * T_ + (t + 1);
#pragma unroll
                for (int nf = 0; nf < 4; nf++) {
                    float2 v = *(const float2*)&zx[row * G_ + nf * U_ + ubase];
                    zq[nf][half * 2 + 0] = v.x;
                    zq[nf][half * 2 + 1] = v.y;
                }
            }
            __threadfence();
            __syncthreads();
            if (tid == 0) {
                atomicAdd(bar, 1u);
                unsigned target = nb * (unsigned)(t + 1);
                volatile unsigned* vb = bar;
                while (*vb < target) { __nanosleep(64); }
            }
            __syncthreads();
        }
    }
}

// ---------------- host launcher ----------------
extern "C" void kernel_launch(void* const* d_in, const int* in_sizes, int n_in,
                              void* d_out, int out_size) {
    const float* x  = (const float*)d_in[0];
    const float* W0 = (const float*)d_in[1];
    const float* U0 = (const float*)d_in[2];
    const float* b0 = (const float*)d_in[3];
    const float* W1 = (const float*)d_in[4];
    const float* U1 = (const float*)d_in[5];
    const float* b1 = (const float*)d_in[6];
    const float* Wd = (const float*)d_in[7];
    const float* bd = (const float*)d_in[8];
    float* out = (float*)d_out;

    __nv_bfloat16 *ahi, *alo, *bhi, *blo, *uhi, *ulo, *hhi, *hlo;
    float *zx_p;
    cudaGetSymbolAddress((void**)&ahi, g_ahi);
    cudaGetSymbolAddress((void**)&alo, g_alo);
    cudaGetSymbolAddress((void**)&bhi, g_bhi);
    cudaGetSymbolAddress((void**)&blo, g_blo);
    cudaGetSymbolAddress((void**)&uhi, g_uhi);
    cudaGetSymbolAddress((void**)&ulo, g_ulo);
    cudaGetSymbolAddress((void**)&hhi, g_hhi);
    cudaGetSymbolAddress((void**)&hlo, g_hlo);
    cudaGetSymbolAddress((void**)&zx_p, g_zx);

    cudaFuncSetAttribute(lstm_kernel, cudaFuncAttributeMaxDynamicSharedMemorySize, LSTM_SMEM);
    cudaFuncSetAttribute(mma_gemm_kernel<false>, cudaFuncAttributeMaxDynamicSharedMemorySize, MM_SMEM);
    cudaFuncSetAttribute(mma_gemm_kernel<true>,  cudaFuncAttributeMaxDynamicSharedMemorySize, MM_SMEM);

    reset_bar_kernel<<<1, 1>>>();

    // x -> (B*T, 960) bf16 hi/lo
    {
        long total = (long)M_ * K0P;
        transpose_x_kernel<<<(int)((total + 255) / 256), 256>>>(x);
    }
    // W0 -> (1024, 960) K-major hi/lo ; U0 -> permuted
    {
        long total = (long)G_ * K0P;
        wtrans_kernel<<<(int)((total + 255) / 256), 256>>>(W0, K0, G_, K0P);
        long tu = (long)G_ * U_;
        utrans_kernel<<<(int)((tu + 255) / 256), 256>>>(U0);
    }
    // zx = x @ W0 + b0
    mma_gemm_kernel<false><<<dim3(G_ / 128, M_ / 128), 256, MM_SMEM>>>(
        ahi, alo, bhi, blo, b0, zx_p, K0P, G_);

    // LSTM layer 0 -> hhi/hlo
    lstm_kernel<<<128, 128, LSTM_SMEM>>>(zx_p, uhi, ulo, hhi, hlo, 0);

    // W1 -> (1024, 256) K-major hi/lo ; U1 -> permuted
    {
        long total = (long)G_ * U_;
        wtrans_kernel<<<(int)((total + 255) / 256), 256>>>(W1, U_, G_, U_);
        utrans_kernel<<<(int)((total + 255) / 256), 256>>>(U1);
    }
    // zx = h0 @ W1 + b1
    mma_gemm_kernel<false><<<dim3(G_ / 128, M_ / 128), 256, MM_SMEM>>>(
        hhi, hlo, bhi, blo, b1, zx_p, U_, G_);

    // LSTM layer 1 -> hhi/hlo (overwrites h0; zx1 GEMM already consumed it)
    lstm_kernel<<<128, 128, LSTM_SMEM>>>(zx_p, uhi, ulo, hhi, hlo, 1);

    // Wd -> (600, 256) K-major hi/lo
    {
        long total = (long)ND * U_;
        wtrans_kernel<<<(int)((total + 255) / 256), 256>>>(Wd, U_, ND, U_);
    }
    // out = h1 @ Wd + bd, scattered to (B, N, T, 2)
    mma_gemm_kernel<true><<<dim3((ND + 127) / 128, M_ / 128), 256, MM_SMEM>>>(
        hhi, hlo, bhi, blo, bd, out, U_, ND);
}

// round 7
// speedup vs baseline: 3.2304x; 1.0948x over previous
#include <cuda_runtime.h>
#include <cuda_bf16.h>
#include <math.h>
#include <stdint.h>

#define B_   256
#define N_   300
#define T_   64
#define FIN  3
#define U_   256
#define G_   1024            // 4*U_
#define K0   900             // N_*FIN
#define K0P  960             // padded to multiple of 64
#define M_   16384           // B_*T_
#define FOUT 2
#define ND   600             // N_*FOUT

// ---------------- scratch (static device globals; no allocation) ----------------
__device__ __nv_bfloat16 g_ahi[(size_t)M_ * K0P];   // x transposed, bf16-hi
__device__ __nv_bfloat16 g_alo[(size_t)M_ * K0P];   // x transposed, bf16-lo
__device__ __nv_bfloat16 g_bhi[(size_t)G_ * K0P];   // weight K-major, bf16-hi (max size)
__device__ __nv_bfloat16 g_blo[(size_t)G_ * K0P];
__device__ __nv_bfloat16 g_uhi[(size_t)G_ * U_];    // recurrent U, permuted K-major, hi
__device__ __nv_bfloat16 g_ulo[(size_t)G_ * U_];
__device__ __nv_bfloat16 g_hhi[(size_t)M_ * U_];    // h sequence bf16-hi
__device__ __nv_bfloat16 g_hlo[(size_t)M_ * U_];    // h sequence bf16-lo
__device__ float    g_zx[(size_t)M_ * G_];          // gate pre-acts
__device__ unsigned g_bar[2][16];                   // per-(layer, batch-tile) counters

__global__ void reset_bar_kernel() {
    int i = threadIdx.x;
    if (i < 16) { g_bar[0][i] = 0u; g_bar[1][i] = 0u; }
}

// single dynamic-smem symbol for all kernels
extern __shared__ char dynsmem[];

// ---------------- bf16 2-term split ----------------
__device__ __forceinline__ void bf16split(float v, __nv_bfloat16& hi, __nv_bfloat16& lo) {
    hi = __float2bfloat16(v);
    lo = __float2bfloat16(v - __bfloat162float(hi));
}

// ---------------- input transpose + split ----------------
__global__ void transpose_x_kernel(const float* __restrict__ x) {
    long i = (long)blockIdx.x * blockDim.x + threadIdx.x;
    if (i >= (long)M_ * K0P) return;
    int  col = (int)(i % K0P);
    long row = i / K0P;
    float v = 0.f;
    if (col < K0) {
        int f = col % FIN;
        int n = col / FIN;
        int t = (int)(row & (T_ - 1));
        int b = (int)(row >> 6);
        v = x[(((long)b * N_ + n) * T_ + t) * FIN + f];
    }
    __nv_bfloat16 hi, lo;
    bf16split(v, hi, lo);
    g_ahi[i] = hi;
    g_alo[i] = lo;
}

// ---------------- weight transpose + split: W (K,N) -> (N, Ks) K-major hi/lo ----------------
__global__ void wtrans_kernel(const float* __restrict__ W, int K, int N, int Ks) {
    long i = (long)blockIdx.x * blockDim.x + threadIdx.x;
    if (i >= (long)N * Ks) return;
    int k = (int)(i % Ks);
    int n = (int)(i / Ks);
    float v = (k < K) ? W[(long)k * N + n] : 0.f;
    __nv_bfloat16 hi, lo;
    bf16split(v, hi, lo);
    g_bhi[i] = hi;
    g_blo[i] = lo;
}

// ---------------- recurrent-U permute + split ----------------
__global__ void utrans_kernel(const float* __restrict__ U) {
    long i = (long)blockIdx.x * blockDim.x + threadIdx.x;
    if (i >= (long)G_ * U_) return;
    int k  = (int)(i & 255);
    int cp = (int)(i >> 8);
    int ublk = cp >> 7;
    int local = cp & 127;
    int warp_n = local >> 5;
    int rem = local & 31;
    int gate = rem >> 3;
    int ul = rem & 7;
    int unit = ublk * 32 + warp_n * 8 + ul;
    float v = U[(long)k * G_ + gate * U_ + unit];
    __nv_bfloat16 hi, lo;
    bf16split(v, hi, lo);
    g_uhi[i] = hi;
    g_ulo[i] = lo;
}

// ================= mma.sync helpers =================
__device__ __forceinline__ uint32_t smem_u32(const void* p) {
    uint32_t a;
    asm("{ .reg .u64 t; cvta.to.shared.u64 t, %1; cvt.u32.u64 %0, t; }" : "=r"(a) : "l"(p));
    return a;
}
__device__ __forceinline__ uint32_t sw128(uint32_t o) { return o ^ ((o >> 3) & 0x70); }

__device__ __forceinline__ void ldsm_x4(uint32_t addr, uint32_t& r0, uint32_t& r1,
                                        uint32_t& r2, uint32_t& r3) {
    asm volatile("ldmatrix.sync.aligned.m8n8.x4.shared.b16 {%0,%1,%2,%3}, [%4];"
                 : "=r"(r0), "=r"(r1), "=r"(r2), "=r"(r3) : "r"(addr));
}

__device__ __forceinline__ void mma_bf16(float* d, const uint32_t* a, uint32_t b0, uint32_t b1) {
    asm volatile(
        "mma.sync.aligned.m16n8k16.row.col.f32.bf16.bf16.f32 "
        "{%0,%1,%2,%3}, {%4,%5,%6,%7}, {%8,%9}, {%0,%1,%2,%3};"
        : "+f"(d[0]), "+f"(d[1]), "+f"(d[2]), "+f"(d[3])
        : "r"(a[0]), "r"(a[1]), "r"(a[2]), "r"(a[3]), "r"(b0), "r"(b1));
}

__device__ __forceinline__ void cp_async16(uint32_t dst, const void* src, uint32_t src_bytes) {
    asm volatile("cp.async.cg.shared.global [%0], [%1], 16, %2;"
                 :: "r"(dst), "l"(src), "r"(src_bytes));
}

// ---------------- tensor-core GEMM (feed-forward): C = A @ B^T + bias ----------------
// 128x128 tile, BK=64, 256 threads, double-buffered cp.async (2 x 64KB stages).
#define ST_A_HI 0
#define ST_A_LO 16384
#define ST_B_HI 32768
#define ST_B_LO 49152
#define STAGE_SZ 65536
#define MM_SMEM  131072

template <bool SCATTER>
__global__ void __launch_bounds__(256, 1)
mma_gemm_kernel(const __nv_bfloat16* __restrict__ Ahi, const __nv_bfloat16* __restrict__ Alo,
                const __nv_bfloat16* __restrict__ Bhi, const __nv_bfloat16* __restrict__ Blo,
                const float* __restrict__ bias, float* __restrict__ C,
                int Ks, int N) {
    char* smem = dynsmem;
    const int tid  = threadIdx.x;
    const int lane = tid & 31;
    const int wid  = tid >> 5;
    const int warp_m = wid >> 2;       // 0..1 -> 64 rows
    const int warp_n = wid & 3;        // 0..3 -> 32 cols
    const int m0 = blockIdx.y * 128;
    const int n0 = blockIdx.x * 128;
    const uint32_t sbase = smem_u32(smem);

    float acc[4][4][4];
#pragma unroll
    for (int i = 0; i < 4; i++)
#pragma unroll
        for (int j = 0; j < 4; j++)
#pragma unroll
            for (int q = 0; q < 4; q++) acc[i][j][q] = 0.f;

    const int iters = Ks >> 6;

    // ---- async stage loader ----
    auto load_stage = [&](int kt, int buf) {
        uint32_t bb = sbase + (uint32_t)buf * STAGE_SZ;
#pragma unroll
        for (int i = 0; i < 4; i++) {
            int idx = tid + i * 256;            // 0..1023
            int r = idx >> 3, kq = idx & 7;
            uint32_t so = sw128((uint32_t)(r * 128 + kq * 16));
            cp_async16(bb + ST_A_HI + so, Ahi + (size_t)(m0 + r) * Ks + kt + kq * 8, 16u);
            cp_async16(bb + ST_A_LO + so, Alo + (size_t)(m0 + r) * Ks + kt + kq * 8, 16u);
            uint32_t vbytes = (n0 + r < N) ? 16u : 0u;
            int rcl = (n0 + r < N) ? (n0 + r) : 0;
            cp_async16(bb + ST_B_HI + so, Bhi + (size_t)rcl * Ks + kt + kq * 8, vbytes);
            cp_async16(bb + ST_B_LO + so, Blo + (size_t)rcl * Ks + kt + kq * 8, vbytes);
        }
        asm volatile("cp.async.commit_group;" ::: "memory");
    };

    load_stage(0, 0);

    for (int it = 0; it < iters; it++) {
        if (it + 1 < iters) {
            load_stage((it + 1) << 6, (it + 1) & 1);
            asm volatile("cp.async.wait_group 1;" ::: "memory");
        } else {
            asm volatile("cp.async.wait_group 0;" ::: "memory");
        }
        __syncthreads();

        uint32_t bb = sbase + (uint32_t)(it & 1) * STAGE_SZ;
#pragma unroll
        for (int ks = 0; ks < 4; ks++) {
            const int kb = ks * 16;
            uint32_t bh[2][4], bl[2][4];
#pragma unroll
            for (int ng = 0; ng < 2; ng++) {
                int nrow = warp_n * 32 + ng * 16 + (lane & 7) + (lane >> 4) * 8;
                int koff = kb + ((lane >> 3) & 1) * 8;
                uint32_t so = sw128((uint32_t)(nrow * 128 + koff * 2));
                ldsm_x4(bb + ST_B_HI + so, bh[ng][0], bh[ng][1], bh[ng][2], bh[ng][3]);
                ldsm_x4(bb + ST_B_LO + so, bl[ng][0], bl[ng][1], bl[ng][2], bl[ng][3]);
            }
#pragma unroll
            for (int mf = 0; mf < 4; mf++) {
                int mrow = warp_m * 64 + mf * 16 + (lane & 7) + ((lane >> 3) & 1) * 8;
                int koff = kb + (lane >> 4) * 8;
                uint32_t so = sw128((uint32_t)(mrow * 128 + koff * 2));
                uint32_t ah[4], al[4];
                ldsm_x4(bb + ST_A_HI + so, ah[0], ah[1], ah[2], ah[3]);
                ldsm_x4(bb + ST_A_LO + so, al[0], al[1], al[2], al[3]);
#pragma unroll
                for (int ng = 0; ng < 2; ng++) {
#pragma unroll
                    for (int h = 0; h < 2; h++) {
                        int nf = ng * 2 + h;
                        mma_bf16(acc[mf][nf], ah, bh[ng][h * 2], bh[ng][h * 2 + 1]);
                        mma_bf16(acc[mf][nf], ah, bl[ng][h * 2], bl[ng][h * 2 + 1]);
                        mma_bf16(acc[mf][nf], al, bh[ng][h * 2], bh[ng][h * 2 + 1]);
                    }
                }
            }
        }
        __syncthreads();
    }

    const int g  = lane >> 2;
    const int tq = lane & 3;
#pragma unroll
    for (int mf = 0; mf < 4; mf++) {
#pragma unroll
        for (int nf = 0; nf < 4; nf++) {
            int c = n0 + warp_n * 32 + nf * 8 + tq * 2;
            if (c >= N) continue;
            float bx = bias[c], by = bias[c + 1];
#pragma unroll
            for (int half = 0; half < 2; half++) {
                int m = m0 + warp_m * 64 + mf * 16 + g + half * 8;
                float vx = acc[mf][nf][half * 2 + 0] + bx;
                float vy = acc[mf][nf][half * 2 + 1] + by;
                if (SCATTER) {
                    int b = m >> 6, t = m & 63;
                    int nn = c >> 1;
                    float2* p = (float2*)&C[(((long)b * N_ + nn) * T_ + t) * FOUT];
                    *p = make_float2(vx, vy);
                } else {
                    *(float2*)&C[(size_t)m * N + c] = make_float2(vx, vy);
                }
            }
        }
    }
}

// ---------------- tensor-core persistent LSTM layer kernel ----------------
// 128 blocks = 16 batch-tiles (M=16) x 8 unit-tiles (128 permuted gate-cols).
// Sync scoped per batch-tile: block only waits for the 8 blocks sharing bblk.
#define SM_U_HI  0                    // 4 panels x 16KB
#define SM_U_LO  65536
#define SM_H_HI  131072               // 4 panels x 2KB
#define SM_H_LO  139264
#define LSTM_SMEM 147456

__global__ void __launch_bounds__(128, 1)
lstm_kernel(const float* __restrict__ zx,   // (M_,1024) rows b*T+t, cols gate*256+unit
            const __nv_bfloat16* __restrict__ Uphi,  // permuted (1024,256) K-major
            const __nv_bfloat16* __restrict__ Uplo,
            __nv_bfloat16* __restrict__ hhi,         // (M_,256) rows b*T+t
            __nv_bfloat16* __restrict__ hlo,
            int bar_idx) {
    char* smem = dynsmem;
    const uint32_t sbase = smem_u32(smem);
    const int tid  = threadIdx.x;
    const int lane = tid & 31;
    const int warp_n = tid >> 5;            // 0..3
    const int ublk = blockIdx.x & 7;
    const int bblk = blockIdx.x >> 3;
    const int b0 = bblk * 16;
    const int cbase = ublk * 128;           // permuted col base

    // ---- load U slice into smem panels (once) ----
    for (int idx = tid; idx < 4096; idx += 128) {
        int n = idx >> 5, kq = idx & 31;
        int k = kq * 8;
        int p = k >> 6, ko = k & 63;
        uint32_t dst = (uint32_t)(p * 16384) + sw128((uint32_t)(n * 128 + ko * 2));
        *(uint4*)(smem + SM_U_HI + dst) = *(const uint4*)(Uphi + (size_t)(cbase + n) * U_ + k);
        *(uint4*)(smem + SM_U_LO + dst) = *(const uint4*)(Uplo + (size_t)(cbase + n) * U_ + k);
    }
    __syncthreads();

    const int g  = lane >> 2;               // row group 0..7
    const int tq = lane & 3;
    const int ubase = ublk * 32 + warp_n * 8 + tq * 2;   // global unit for e=0

    unsigned* bar = &g_bar[bar_idx][bblk];

    float cst[4] = {0.f, 0.f, 0.f, 0.f};
    float zq[4][4];

    // prefetch zx for t=0
#pragma unroll
    for (int half = 0; half < 2; half++) {
        long row = (long)(b0 + half * 8 + g) * T_ + 0;
#pragma unroll
        for (int nf = 0; nf < 4; nf++) {
            float2 v = *(const float2*)&zx[row * G_ + nf * U_ + ubase];
            zq[nf][half * 2 + 0] = v.x;
            zq[nf][half * 2 + 1] = v.y;
        }
    }

    for (int t = 0; t < T_; t++) {
        float acc[4][4];
#pragma unroll
        for (int nf = 0; nf < 4; nf++)
#pragma unroll
            for (int q = 0; q < 4; q++) acc[nf][q] = 0.f;

        if (t > 0) {
            // stage h_{t-1} tile: 16 rows x 256 k, hi+lo
#pragma unroll
            for (int j = 0; j < 4; j++) {
                int idx = tid + j * 128;         // 0..511
                int r = idx >> 5, kq = idx & 31;
                int k = kq * 8;
                int p = k >> 6, ko = k & 63;
                long src = ((long)(b0 + r) * T_ + (t - 1)) * U_ + k;
                uint32_t dst = (uint32_t)(p * 2048) + sw128((uint32_t)(r * 128 + ko * 2));
                *(uint4*)(smem + SM_H_HI + dst) = *(const uint4*)(hhi + src);
                *(uint4*)(smem + SM_H_LO + dst) = *(const uint4*)(hlo + src);
            }
            __syncthreads();

#pragma unroll
            for (int kc = 0; kc < 16; kc++) {
                const int p = kc >> 2;
                const int kb = (kc & 3) * 16;
                int mrow = (lane & 7) + ((lane >> 3) & 1) * 8;
                int koffA = kb + (lane >> 4) * 8;
                uint32_t soA = (uint32_t)(p * 2048) + sw128((uint32_t)(mrow * 128 + koffA * 2));
                uint32_t ah[4], al[4];
                ldsm_x4(sbase + SM_H_HI + soA, ah[0], ah[1], ah[2], ah[3]);
                ldsm_x4(sbase + SM_H_LO + soA, al[0], al[1], al[2], al[3]);
                uint32_t bh[2][4], bl[2][4];
#pragma unroll
                for (int ng = 0; ng < 2; ng++) {
                    int nrow = warp_n * 32 + ng * 16 + (lane & 7) + (lane >> 4) * 8;
                    int koffB = kb + ((lane >> 3) & 1) * 8;
                    uint32_t soB = (uint32_t)(p * 16384) + sw128((uint32_t)(nrow * 128 + koffB * 2));
                    ldsm_x4(sbase + SM_U_HI + soB, bh[ng][0], bh[ng][1], bh[ng][2], bh[ng][3]);
                    ldsm_x4(sbase + SM_U_LO + soB, bl[ng][0], bl[ng][1], bl[ng][2], bl[ng][3]);
                }
#pragma unroll
                for (int ng = 0; ng < 2; ng++) {
#pragma unroll
                    for (int h = 0; h < 2; h++) {
                        int nf = ng * 2 + h;
                        mma_bf16(acc[nf], ah, bh[ng][h * 2], bh[ng][h * 2 + 1]);
                        mma_bf16(acc[nf], ah, bl[ng][h * 2], bl[ng][h * 2 + 1]);
                        mma_bf16(acc[nf], al, bh[ng][h * 2], bh[ng][h * 2 + 1]);
                    }
                }
            }
        }

        // gates (i,f,g,o) + state update + packed bf16 h store
#pragma unroll
        for (int half = 0; half < 2; half++) {
            long row = (long)(b0 + half * 8 + g) * T_ + t;
            __nv_bfloat16 phi[2], plo[2];
#pragma unroll
            for (int e = 0; e < 2; e++) {
                int q = half * 2 + e;
                float ig = 1.f / (1.f + expf(-(zq[0][q] + acc[0][q])));
                float fg = 1.f / (1.f + expf(-(zq[1][q] + acc[1][q])));
                float gg = fmaxf(zq[2][q] + acc[2][q], 0.f);
                float og = 1.f / (1.f + expf(-(zq[3][q] + acc[3][q])));
                float c  = fg * cst[q] + ig * gg;
                cst[q] = c;
                float h = og * fmaxf(c, 0.f);
                bf16split(h, phi[e], plo[e]);
            }
            *(uint32_t*)&hhi[row * U_ + ubase] = ((uint32_t)*(uint16_t*)&phi[1] << 16) |
                                                 (uint32_t)*(uint16_t*)&phi[0];
            *(uint32_t*)&hlo[row * U_ + ubase] = ((uint32_t)*(uint16_t*)&plo[1] << 16) |
                                                 (uint32_t)*(uint16_t*)&plo[0];
        }

        if (t < T_ - 1) {
            // prefetch zx for t+1 (overlaps with barrier wait)
#pragma unroll
            for (int half = 0; half < 2; half++) {
                long row = (long)(b0 + half * 8 + g) * T_ + (t + 1);
#pragma unroll
                for (int nf = 0; nf < 4; nf++) {
                    float2 v = *(const float2*)&zx[row * G_ + nf * U_ + ubase];
                    zq[nf][half * 2 + 0] = v.x;
                    zq[nf][half * 2 + 1] = v.y;
                }
            }
            // per-batch-tile barrier: only the 8 unit-tile blocks of this bblk
            __threadfence();
            __syncthreads();
            if (tid == 0) {
                atomicAdd(bar, 1u);
                unsigned target = 8u * (unsigned)(t + 1);
                volatile unsigned* vb = bar;
                while (*vb < target) { __nanosleep(32); }
            }
            __syncthreads();
        }
    }
}

// ---------------- host launcher ----------------
extern "C" void kernel_launch(void* const* d_in, const int* in_sizes, int n_in,
                              void* d_out, int out_size) {
    const float* x  = (const float*)d_in[0];
    const float* W0 = (const float*)d_in[1];
    const float* U0 = (const float*)d_in[2];
    const float* b0 = (const float*)d_in[3];
    const float* W1 = (const float*)d_in[4];
    const float* U1 = (const float*)d_in[5];
    const float* b1 = (const float*)d_in[6];
    const float* Wd = (const float*)d_in[7];
    const float* bd = (const float*)d_in[8];
    float* out = (float*)d_out;

    __nv_bfloat16 *ahi, *alo, *bhi, *blo, *uhi, *ulo, *hhi, *hlo;
    float *zx_p;
    cudaGetSymbolAddress((void**)&ahi, g_ahi);
    cudaGetSymbolAddress((void**)&alo, g_alo);
    cudaGetSymbolAddress((void**)&bhi, g_bhi);
    cudaGetSymbolAddress((void**)&blo, g_blo);
    cudaGetSymbolAddress((void**)&uhi, g_uhi);
    cudaGetSymbolAddress((void**)&ulo, g_ulo);
    cudaGetSymbolAddress((void**)&hhi, g_hhi);
    cudaGetSymbolAddress((void**)&hlo, g_hlo);
    cudaGetSymbolAddress((void**)&zx_p, g_zx);

    cudaFuncSetAttribute(lstm_kernel, cudaFuncAttributeMaxDynamicSharedMemorySize, LSTM_SMEM);
    cudaFuncSetAttribute(mma_gemm_kernel<false>, cudaFuncAttributeMaxDynamicSharedMemorySize, MM_SMEM);
    cudaFuncSetAttribute(mma_gemm_kernel<true>,  cudaFuncAttributeMaxDynamicSharedMemorySize, MM_SMEM);

    reset_bar_kernel<<<1, 32>>>();

    // x -> (B*T, 960) bf16 hi/lo
    {
        long total = (long)M_ * K0P;
        transpose_x_kernel<<<(int)((total + 255) / 256), 256>>>(x);
    }
    // W0 -> (1024, 960) K-major hi/lo ; U0 -> permuted
    {
        long total = (long)G_ * K0P;
        wtrans_kernel<<<(int)((total + 255) / 256), 256>>>(W0, K0, G_, K0P);
        long tu = (long)G_ * U_;
        utrans_kernel<<<(int)((tu + 255) / 256), 256>>>(U0);
    }
    // zx = x @ W0 + b0
    mma_gemm_kernel<false><<<dim3(G_ / 128, M_ / 128), 256, MM_SMEM>>>(
        ahi, alo, bhi, blo, b0, zx_p, K0P, G_);

    // LSTM layer 0 -> hhi/hlo
    lstm_kernel<<<128, 128, LSTM_SMEM>>>(zx_p, uhi, ulo, hhi, hlo, 0);

    // W1 -> (1024, 256) K-major hi/lo ; U1 -> permuted
    {
        long total = (long)G_ * U_;
        wtrans_kernel<<<(int)((total + 255) / 256), 256>>>(W1, U_, G_, U_);
        utrans_kernel<<<(int)((total + 255) / 256), 256>>>(U1);
    }
    // zx = h0 @ W1 + b1
    mma_gemm_kernel<false><<<dim3(G_ / 128, M_ / 128), 256, MM_SMEM>>>(
        hhi, hlo, bhi, blo, b1, zx_p, U_, G_);

    // LSTM layer 1 -> hhi/hlo
    lstm_kernel<<<128, 128, LSTM_SMEM>>>(zx_p, uhi, ulo, hhi, hlo, 1);

    // Wd -> (600, 256) K-major hi/lo
    {
        long total = (long)ND * U_;
        wtrans_kernel<<<(int)((total + 255) / 256), 256>>>(Wd, U_, ND, U_);
    }
    // out = h1 @ Wd + bd, scattered to (B, N, T, 2)
    mma_gemm_kernel<true><<<dim3((ND + 127) / 128, M_ / 128), 256, MM_SMEM>>>(
        hhi, hlo, bhi, blo, bd, out, U_, ND);
}